// round 8
// baseline (speedup 1.0000x reference)
#include <cuda_runtime.h>
#include <math.h>

#define BB 8
#define SS 200
#define HH 4
#define DD 64
#define HID 256
#define NBS (BB*SS)   // 1600

// scratch (device globals; no allocation allowed)
__device__ float g_q[NBS*HID];
__device__ float g_k[NBS*HID];
__device__ float g_kpos[NBS*HID];
__device__ float g_vpos[NBS*HID];
__device__ float g_qo[BB*HH*SS];
__device__ float g_ko[BB*HH*SS];
__device__ float g_qd[BB*HH*SS];
__device__ float g_kd[BB*HH*SS];
__device__ float g_qk[NBS*HH*SS];      // q_i . kpos_j  [b][i][h][j]
__device__ float g_probs[NBS*HH*SS];   // normalized probs, [b][i][h][j]
__device__ float g_ctx[NBS*HID];       // sum_j p * timeV
__device__ float g_ctxp[NBS*HID];      // probs @ vpos

// ---------------------------------------------------------------------------
// Kernel 1: one (8-row, matrix) tile per block; split-K x4 inside the block.
// ---------------------------------------------------------------------------
__global__ __launch_bounds__(256) void gemm3_kernel(
    const float* __restrict__ x,
    const float* __restrict__ Wq, const float* __restrict__ bq,
    const float* __restrict__ Wk, const float* __restrict__ bk,
    const float* __restrict__ Wv, const float* __restrict__ bv,
    const float* __restrict__ posV)
{
    const int r0  = blockIdx.x * 8;
    const int mat = blockIdx.y;
    const float* __restrict__ W    = (mat == 0) ? Wq : (mat == 1) ? Wk : Wv;
    const float* __restrict__ bias = (mat == 0) ? bq : (mat == 1) ? bk : bv;

    const int tid = threadIdx.x;
    const int s   = tid >> 6;
    const int c   = tid & 63;

    __shared__ float xs[HID][8];
    __shared__ float red[3][8][HID];

    for (int t = tid; t < 8 * HID; t += 256) {
        const int m = t >> 8, g = t & 255;
        xs[g][m] = x[(r0 + m) * HID + g];
    }
    __syncthreads();

    float4 acc[8];
    if (s == 0) {
        const float4 b4 = *(const float4*)&bias[4 * c];
        #pragma unroll
        for (int m = 0; m < 8; m++) acc[m] = b4;
    } else {
        #pragma unroll
        for (int m = 0; m < 8; m++) acc[m] = make_float4(0.f, 0.f, 0.f, 0.f);
    }

    const float* __restrict__ Wp = W + (size_t)(s * 64) * HID + 4 * c;
    const float* __restrict__ xp = &xs[s * 64][0];
    #pragma unroll 4
    for (int gi = 0; gi < 64; gi++) {
        const float4 w = *(const float4*)(Wp + (size_t)gi * HID);
        #pragma unroll
        for (int m = 0; m < 8; m++) {
            const float xv = xp[gi * 8 + m];
            acc[m].x += xv * w.x; acc[m].y += xv * w.y;
            acc[m].z += xv * w.z; acc[m].w += xv * w.w;
        }
    }

    if (s > 0) {
        #pragma unroll
        for (int m = 0; m < 8; m++)
            *(float4*)&red[s - 1][m][4 * c] = acc[m];
    }
    __syncthreads();

    if (s == 0) {
        #pragma unroll
        for (int m = 0; m < 8; m++) {
            const float4 r0v = *(const float4*)&red[0][m][4 * c];
            const float4 r1v = *(const float4*)&red[1][m][4 * c];
            const float4 r2v = *(const float4*)&red[2][m][4 * c];
            float4 a = acc[m];
            a.x += r0v.x + r1v.x + r2v.x;
            a.y += r0v.y + r1v.y + r2v.y;
            a.z += r0v.z + r1v.z + r2v.z;
            a.w += r0v.w + r1v.w + r2v.w;
            const int row = r0 + m;
            if (mat == 0) {
                *(float4*)&g_q[(size_t)row * HID + 4 * c] = a;
            } else if (mat == 1) {
                *(float4*)&g_k[(size_t)row * HID + 4 * c] = a;
            } else {
                const float4 pv = *(const float4*)&posV[(size_t)row * HID + 4 * c];
                a.x += pv.x; a.y += pv.y; a.z += pv.z; a.w += pv.w;
                *(float4*)&g_vpos[(size_t)row * HID + 4 * c] = a;
            }
        }
    }
}

// ---------------------------------------------------------------------------
// Kernel 1b: kpos = k + posK; order/dist scalar dot tables. 8 rows/block.
// ---------------------------------------------------------------------------
__global__ __launch_bounds__(256) void post_kernel(
    const float* __restrict__ posK,
    const float* __restrict__ order_w, const float* __restrict__ dist_w)
{
    const int f  = threadIdx.x;
    const int r0 = blockIdx.x * 8;

    __shared__ float qs[8][HID];
    __shared__ float ks[8][HID];

    #pragma unroll
    for (int m = 0; m < 8; m++) {
        const int row = r0 + m;
        const float kv = g_k[(size_t)row * HID + f];
        qs[m][f] = g_q[(size_t)row * HID + f];
        ks[m][f] = kv;
        g_kpos[(size_t)row * HID + f] = kv + posK[(size_t)row * HID + f];
    }
    __syncthreads();

    const int w = f >> 5, l = f & 31;
    const int row = r0 + w;
    const int b = row / SS, sidx = row % SS;
    #pragma unroll
    for (int h = 0; h < HH; h++) {
        float qo = qs[w][h*64 + l] * order_w[l]      + qs[w][h*64 + 32 + l] * order_w[32 + l];
        float qd = qs[w][h*64 + l] * dist_w[l]       + qs[w][h*64 + 32 + l] * dist_w[32 + l];
        float ko = ks[w][h*64 + l] * order_w[64 + l] + ks[w][h*64 + 32 + l] * order_w[96 + l];
        float kd = ks[w][h*64 + l] * dist_w[64 + l]  + ks[w][h*64 + 32 + l] * dist_w[96 + l];
        #pragma unroll
        for (int off = 16; off; off >>= 1) {
            qo += __shfl_xor_sync(0xffffffffu, qo, off);
            qd += __shfl_xor_sync(0xffffffffu, qd, off);
            ko += __shfl_xor_sync(0xffffffffu, ko, off);
            kd += __shfl_xor_sync(0xffffffffu, kd, off);
        }
        if (l == 0) {
            const int idx = (b * HH + h) * SS + sidx;
            g_qo[idx] = qo; g_qd[idx] = qd; g_ko[idx] = ko; g_kd[idx] = kd;
        }
    }
}

// ---------------------------------------------------------------------------
// Kernel 1c: qk[b][i][h][j] = q_i . kpos_j. Block = 8 i-rows x 100 j (grid
// (200,2)). 8 warps; warp-dot with 8-lane/head reduction.
// ---------------------------------------------------------------------------
__global__ __launch_bounds__(256) void qk_kernel()
{
    const int r0 = blockIdx.x * 8;
    const int jh = blockIdx.y;
    const int b = r0 / SS, i0 = r0 % SS;
    const int tid = threadIdx.x, w = tid >> 5, l = tid & 31;

    __shared__ float q_sh[8][HID];
    for (int t = tid; t < 8 * HID; t += 256)
        q_sh[t >> 8][t & 255] = g_q[(size_t)(r0 + (t >> 8)) * HID + (t & 255)];
    __syncthreads();

    const int hh = l >> 3;
    const float* kpb = g_kpos + (size_t)b * SS * HID;
    const int j0 = jh * 100;

    for (int j = j0 + w; j < j0 + 100; j += 8) {
        const float4* kp = (const float4*)(kpb + (size_t)j * HID);
        const float4 k0 = kp[2 * l], k1 = kp[2 * l + 1];
        #pragma unroll
        for (int it = 0; it < 8; it++) {
            const float4 q0 = *(const float4*)&q_sh[it][l * 8];
            const float4 q1 = *(const float4*)&q_sh[it][l * 8 + 4];
            float p = q0.x * k0.x + q0.y * k0.y + q0.z * k0.z + q0.w * k0.w
                    + q1.x * k1.x + q1.y * k1.y + q1.z * k1.z + q1.w * k1.w;
            p += __shfl_xor_sync(0xffffffffu, p, 1);
            p += __shfl_xor_sync(0xffffffffu, p, 2);
            p += __shfl_xor_sync(0xffffffffu, p, 4);
            if ((l & 7) == 0)
                g_qk[((size_t)(b * SS + i0 + it) * HH + hh) * SS + j] = p;
        }
    }
}

// ---------------------------------------------------------------------------
// Kernel 2a: scores + softmax. ITA=2 rows/block, 256 threads, grid 800.
// Streams ONLY timeK (kpos folded in via g_qk).
// ---------------------------------------------------------------------------
#define ITA 2
__global__ __launch_bounds__(256) void score_kernel(
    const float* __restrict__ timeK,
    const float* __restrict__ mask,
    const float* __restrict__ p_order_b, const float* __restrict__ p_dist_b,
    const float* __restrict__ p_scalar)
{
    const int tid = threadIdx.x;
    const int blk = blockIdx.x;
    const int b  = blk / (SS / ITA);
    const int i0 = (blk % (SS / ITA)) * ITA;
    const int w = tid >> 5, l = tid & 31;

    __shared__ float sc[ITA][HH][SS];
    __shared__ float q_sh[ITA][HID];
    __shared__ float qos[ITA][HH], qds[ITA][HH];
    __shared__ float inv_s[ITA][HH];
    __shared__ float dl[SS];

    #pragma unroll
    for (int it = 0; it < ITA; it++)
        q_sh[it][tid] = g_q[((size_t)(b * SS + i0 + it)) * HID + tid];
    if (tid < ITA * HH) {
        const int it = tid >> 2, h = tid & 3;
        qos[it][h] = g_qo[(b * HH + h) * SS + i0 + it];
        qds[it][h] = g_qd[(b * HH + h) * SS + i0 + it];
    }
    if (tid < SS) dl[tid] = __logf((float)tid + 1.f);
    __syncthreads();

    float4 q0[ITA], q1[ITA];
    #pragma unroll
    for (int it = 0; it < ITA; it++) {
        q0[it] = *(const float4*)&q_sh[it][l * 8];
        q1[it] = *(const float4*)&q_sh[it][l * 8 + 4];
    }
    const int hh = l >> 3;

    const float* tk0 = timeK + ((size_t)(b * SS + i0))     * SS * HID;
    const float* tk1 = timeK + ((size_t)(b * SS + i0 + 1)) * SS * HID;

    // ---- phase 1: q . timeK only ----
    for (int j = w; j < SS; j += 8) {
        const float4* ta0 = (const float4*)(tk0 + (size_t)j * HID);
        const float4* ta1 = (const float4*)(tk1 + (size_t)j * HID);
        const float4 a0 = ta0[2 * l], a1 = ta0[2 * l + 1];
        const float4 b0 = ta1[2 * l], b1 = ta1[2 * l + 1];

        float p0 = q0[0].x * a0.x + q0[0].y * a0.y + q0[0].z * a0.z + q0[0].w * a0.w
                 + q1[0].x * a1.x + q1[0].y * a1.y + q1[0].z * a1.z + q1[0].w * a1.w;
        float p1 = q0[1].x * b0.x + q0[1].y * b0.y + q0[1].z * b0.z + q0[1].w * b0.w
                 + q1[1].x * b1.x + q1[1].y * b1.y + q1[1].z * b1.z + q1[1].w * b1.w;
        p0 += __shfl_xor_sync(0xffffffffu, p0, 1);
        p0 += __shfl_xor_sync(0xffffffffu, p0, 2);
        p0 += __shfl_xor_sync(0xffffffffu, p0, 4);
        p1 += __shfl_xor_sync(0xffffffffu, p1, 1);
        p1 += __shfl_xor_sync(0xffffffffu, p1, 2);
        p1 += __shfl_xor_sync(0xffffffffu, p1, 4);
        if ((l & 7) == 0) { sc[0][hh][j] = p0; sc[1][hh][j] = p1; }
    }
    __syncthreads();

    // ---- phase 2: add qk, order/dist error terms, scale, mask ----
    const float order_b = *p_order_b;
    const float dist_b  = *p_dist_b;
    const float sc2 = p_scalar[0] * p_scalar[0] * 0.5f;
    for (int idx = tid; idx < ITA * HH * SS; idx += 256) {
        const int it = idx / (HH * SS);
        const int rem = idx - it * (HH * SS);
        const int h = rem / SS, j = rem - (rem / SS) * SS;
        const int i = i0 + it;
        const float qkv = g_qk[((size_t)(b * SS + i) * HH + h) * SS + j];
        const float z = qos[it][h] + g_ko[(b * HH + h) * SS + j] + order_b;
        const float zz = (j > i) ? -z : z;     // log-sigmoid via softplus
        const float eo = -(fmaxf(zz, 0.f) + __logf(1.f + __expf(-fabsf(zz))));
        const float gd = dl[abs(j - i)];
        const float pd = qds[it][h] + g_kd[(b * HH + h) * SS + j] + dist_b;
        const float ed = -(gd - pd) * (gd - pd) * sc2;
        sc[it][h][j] = (sc[it][h][j] + qkv + eo + ed) * 0.125f
                     + mask[((size_t)b * SS + i) * SS + j];
    }
    __syncthreads();

    // ---- phase 3: softmax (warp per (it,h) pair; 8 warps = 8 pairs) ----
    {
        const int it = w >> 2, h = w & 3;
        float m = -1e30f;
        for (int j = l; j < SS; j += 32) m = fmaxf(m, sc[it][h][j]);
        #pragma unroll
        for (int off = 16; off; off >>= 1)
            m = fmaxf(m, __shfl_xor_sync(0xffffffffu, m, off));
        float sum = 0.f;
        for (int j = l; j < SS; j += 32) {
            const float e = __expf(sc[it][h][j] - m);
            sc[it][h][j] = e;
            sum += e;
        }
        #pragma unroll
        for (int off = 16; off; off >>= 1)
            sum += __shfl_xor_sync(0xffffffffu, sum, off);
        if (l == 0) inv_s[it][h] = 1.f / sum;
    }
    __syncthreads();

    // ---- write normalized probs ----
    for (int idx = tid; idx < ITA * HH * SS; idx += 256) {
        const int it = idx / (HH * SS);
        const int rem = idx - it * (HH * SS);
        const int h = rem / SS, j = rem - (rem / SS) * SS;
        g_probs[((size_t)(b * SS + i0 + it) * HH + h) * SS + j]
            = sc[it][h][j] * inv_s[it][h];
    }
}

// ---------------------------------------------------------------------------
// Kernel 2b: ctxp = probs @ vpos. Block = 4 i-rows, 256 threads = f. grid 400.
// ---------------------------------------------------------------------------
__global__ __launch_bounds__(256) void pv_kernel()
{
    const int r0 = blockIdx.x * 4;
    const int b = r0 / SS, i0 = r0 % SS;
    const int tid = threadIdx.x;

    __shared__ float pr[4][HH * SS];   // 12.8KB

    for (int t = tid; t < 4 * HH * SS; t += 256) {
        const int it = t / (HH * SS);
        const int rem = t - it * (HH * SS);
        pr[it][rem] = g_probs[((size_t)(b * SS + i0 + it) * HH) * SS + rem];
    }
    __syncthreads();

    const int f = tid;
    const int h = f >> 6;
    const float* vp = g_vpos + (size_t)b * SS * HID + f;

    float acc[4] = {0.f, 0.f, 0.f, 0.f};
    #pragma unroll 4
    for (int j = 0; j < SS; j++) {
        const float v = vp[(size_t)j * HID];
        #pragma unroll
        for (int it = 0; it < 4; it++)
            acc[it] += pr[it][h * SS + j] * v;
    }
    #pragma unroll
    for (int it = 0; it < 4; it++)
        g_ctxp[((size_t)(b * SS + i0 + it)) * HID + f] = acc[it];
}

// ---------------------------------------------------------------------------
// Kernel 2c: ctx = sum_j p * timeV. One i-row per block, split-j x4,
// 256 threads, grid 1600. Streams ONLY timeV.
// ---------------------------------------------------------------------------
__global__ __launch_bounds__(256) void ctx_kernel(
    const float* __restrict__ timeV)
{
    const int tid = threadIdx.x;
    const int blk = blockIdx.x;
    const int b = blk / SS, i = blk % SS;

    const int grp = tid >> 6;         // j-quarter 0..3 (50 j each)
    const int fq  = tid & 63;         // float4 index; f = 4*fq
    const int h   = fq >> 4;

    __shared__ float pr[HH * SS];      // 3.2KB
    __shared__ float4 part[3][64];     // 3KB

    for (int t = tid; t < HH * SS; t += 256)
        pr[t] = g_probs[((size_t)(b * SS + i) * HH) * SS + t];
    __syncthreads();

    const float4* tv = (const float4*)(timeV + ((size_t)(b * SS + i)) * SS * HID) + fq;
    const float* prow = &pr[h * SS];

    const int j0 = grp * (SS / 4);
    float4 acc = make_float4(0.f, 0.f, 0.f, 0.f);
    #pragma unroll 5
    for (int j = j0; j < j0 + SS / 4; j++) {
        const float p = prow[j];
        const float4 t4 = tv[(size_t)j * (HID / 4)];
        acc.x += p * t4.x;
        acc.y += p * t4.y;
        acc.z += p * t4.z;
        acc.w += p * t4.w;
    }

    if (grp > 0) part[grp - 1][fq] = acc;
    __syncthreads();
    if (grp == 0) {
        #pragma unroll
        for (int g = 0; g < 3; g++) {
            const float4 p4 = part[g][fq];
            acc.x += p4.x; acc.y += p4.y; acc.z += p4.z; acc.w += p4.w;
        }
        *(float4*)&g_ctx[((size_t)(b * SS + i)) * HID + 4 * fq] = acc;
    }
}

// ---------------------------------------------------------------------------
// Kernel 3: output projection, 4 rows/block (grid 400) + residual + LN.
// Reads ctx = g_ctx + g_ctxp.
// ---------------------------------------------------------------------------
__global__ __launch_bounds__(256) void outln_kernel(
    const float* __restrict__ x,
    const float* __restrict__ Wd, const float* __restrict__ bd,
    const float* __restrict__ ln_g, const float* __restrict__ ln_b,
    float* __restrict__ out)
{
    const int r0  = blockIdx.x * 4;
    const int tid = threadIdx.x;
    const int s   = tid >> 6;
    const int c   = tid & 63;

    __shared__ float cs[HID][4];
    __shared__ float red[3][4][HID];
    __shared__ float hsm[4][HID];
    __shared__ float mu[4], rstd[4];

    for (int t = tid; t < 4 * HID; t += 256) {
        const int m = t >> 8, g = t & 255;
        cs[g][m] = g_ctx[(size_t)(r0 + m) * HID + g]
                 + g_ctxp[(size_t)(r0 + m) * HID + g];
    }
    __syncthreads();

    float4 acc[4];
    if (s == 0) {
        const float4 b4 = *(const float4*)&bd[4 * c];
        #pragma unroll
        for (int m = 0; m < 4; m++) acc[m] = b4;
    } else {
        #pragma unroll
        for (int m = 0; m < 4; m++) acc[m] = make_float4(0.f, 0.f, 0.f, 0.f);
    }

    const float* __restrict__ Wp = Wd + (size_t)(s * 64) * HID + 4 * c;
    const float* __restrict__ xp = &cs[s * 64][0];
    #pragma unroll 4
    for (int gi = 0; gi < 64; gi++) {
        const float4 w = *(const float4*)(Wp + (size_t)gi * HID);
        #pragma unroll
        for (int m = 0; m < 4; m++) {
            const float xv = xp[gi * 4 + m];
            acc[m].x += xv * w.x; acc[m].y += xv * w.y;
            acc[m].z += xv * w.z; acc[m].w += xv * w.w;
        }
    }

    if (s > 0) {
        #pragma unroll
        for (int m = 0; m < 4; m++)
            *(float4*)&red[s - 1][m][4 * c] = acc[m];
    }
    __syncthreads();

    if (s == 0) {
        #pragma unroll
        for (int m = 0; m < 4; m++) {
            const float4 p0 = *(const float4*)&red[0][m][4 * c];
            const float4 p1 = *(const float4*)&red[1][m][4 * c];
            const float4 p2 = *(const float4*)&red[2][m][4 * c];
            const float4 xv = *(const float4*)&x[(size_t)(r0 + m) * HID + 4 * c];
            float4 a = acc[m];
            a.x += p0.x + p1.x + p2.x + xv.x;
            a.y += p0.y + p1.y + p2.y + xv.y;
            a.z += p0.z + p1.z + p2.z + xv.z;
            a.w += p0.w + p1.w + p2.w + xv.w;
            *(float4*)&hsm[m][4 * c] = a;
        }
    }
    __syncthreads();

    const int w = tid >> 5, l = tid & 31;
    if (w < 4) {
        float sum = 0.f, sum2 = 0.f;
        #pragma unroll
        for (int t = 0; t < 8; t++) {
            const float v = hsm[w][l + 32 * t];
            sum += v; sum2 += v * v;
        }
        #pragma unroll
        for (int off = 16; off; off >>= 1) {
            sum  += __shfl_xor_sync(0xffffffffu, sum,  off);
            sum2 += __shfl_xor_sync(0xffffffffu, sum2, off);
        }
        if (l == 0) {
            const float m_  = sum / HID;
            const float var = sum2 / HID - m_ * m_;
            mu[w]   = m_;
            rstd[w] = rsqrtf(var + 1e-12f);
        }
    }
    __syncthreads();

    const int f = tid;
    const float gf = ln_g[f], bf = ln_b[f];
    #pragma unroll
    for (int m = 0; m < 4; m++)
        out[(size_t)(r0 + m) * HID + f] = (hsm[m][f] - mu[m]) * rstd[m] * gf + bf;
}

// ---------------------------------------------------------------------------
extern "C" void kernel_launch(void* const* d_in, const int* in_sizes, int n_in,
                              void* d_out, int out_size)
{
    const float* x     = (const float*)d_in[0];
    const float* mask  = (const float*)d_in[1];
    const float* posK  = (const float*)d_in[2];
    const float* posV  = (const float*)d_in[3];
    const float* timeK = (const float*)d_in[4];
    const float* timeV = (const float*)d_in[5];
    const float* Wq = (const float*)d_in[6];  const float* bq = (const float*)d_in[7];
    const float* Wk = (const float*)d_in[8];  const float* bk = (const float*)d_in[9];
    const float* Wv = (const float*)d_in[10]; const float* bv = (const float*)d_in[11];
    const float* ow = (const float*)d_in[12]; const float* ob = (const float*)d_in[13];
    const float* dw = (const float*)d_in[14]; const float* db = (const float*)d_in[15];
    const float* sca = (const float*)d_in[16];
    const float* Wd = (const float*)d_in[17]; const float* bd = (const float*)d_in[18];
    const float* lg = (const float*)d_in[19]; const float* lb = (const float*)d_in[20];

    dim3 g1(NBS / 8, 3);
    gemm3_kernel<<<g1, 256>>>(x, Wq, bq, Wk, bk, Wv, bv, posV);
    post_kernel<<<NBS / 8, 256>>>(posK, ow, dw);
    dim3 gqk(NBS / 8, 2);
    qk_kernel<<<gqk, 256>>>();
    score_kernel<<<NBS / ITA, 256>>>(timeK, mask, ob, db, sca);
    pv_kernel<<<NBS / 4, 256>>>();
    ctx_kernel<<<NBS, 256>>>(timeV);
    outln_kernel<<<NBS / 4, 256>>>(x, Wd, bd, lg, lb, (float*)d_out);
}

// round 9
// speedup vs baseline: 1.3608x; 1.3608x over previous
#include <cuda_runtime.h>
#include <math.h>

#define BB 8
#define SS 200
#define HH 4
#define DD 64
#define HID 256
#define NBS (BB*SS)   // 1600

// scratch (device globals; no allocation allowed)
__device__ float g_q[NBS*HID];
__device__ float g_k[NBS*HID];
__device__ float g_kpos[NBS*HID];
__device__ float g_vpos[NBS*HID];
__device__ float g_qo[BB*HH*SS];
__device__ float g_ko[BB*HH*SS];
__device__ float g_qd[BB*HH*SS];
__device__ float g_kd[BB*HH*SS];
__device__ float g_probs[NBS*HH*SS];   // normalized probs, [b][i][h][j]
__device__ float g_ctx[NBS*HID];

// ---------------------------------------------------------------------------
// Kernel 1: one (8-row, matrix) tile per block; split-K x4 inside the block.
// ---------------------------------------------------------------------------
__global__ __launch_bounds__(256) void gemm3_kernel(
    const float* __restrict__ x,
    const float* __restrict__ Wq, const float* __restrict__ bq,
    const float* __restrict__ Wk, const float* __restrict__ bk,
    const float* __restrict__ Wv, const float* __restrict__ bv,
    const float* __restrict__ posV)
{
    const int r0  = blockIdx.x * 8;
    const int mat = blockIdx.y;
    const float* __restrict__ W    = (mat == 0) ? Wq : (mat == 1) ? Wk : Wv;
    const float* __restrict__ bias = (mat == 0) ? bq : (mat == 1) ? bk : bv;

    const int tid = threadIdx.x;
    const int s   = tid >> 6;
    const int c   = tid & 63;

    __shared__ float xs[HID][8];
    __shared__ float red[3][8][HID];

    for (int t = tid; t < 8 * HID; t += 256) {
        const int m = t >> 8, g = t & 255;
        xs[g][m] = x[(r0 + m) * HID + g];
    }
    __syncthreads();

    float4 acc[8];
    if (s == 0) {
        const float4 b4 = *(const float4*)&bias[4 * c];
        #pragma unroll
        for (int m = 0; m < 8; m++) acc[m] = b4;
    } else {
        #pragma unroll
        for (int m = 0; m < 8; m++) acc[m] = make_float4(0.f, 0.f, 0.f, 0.f);
    }

    const float* __restrict__ Wp = W + (size_t)(s * 64) * HID + 4 * c;
    const float* __restrict__ xp = &xs[s * 64][0];
    #pragma unroll 4
    for (int gi = 0; gi < 64; gi++) {
        const float4 w = *(const float4*)(Wp + (size_t)gi * HID);
        #pragma unroll
        for (int m = 0; m < 8; m++) {
            const float xv = xp[gi * 8 + m];
            acc[m].x += xv * w.x; acc[m].y += xv * w.y;
            acc[m].z += xv * w.z; acc[m].w += xv * w.w;
        }
    }

    if (s > 0) {
        #pragma unroll
        for (int m = 0; m < 8; m++)
            *(float4*)&red[s - 1][m][4 * c] = acc[m];
    }
    __syncthreads();

    if (s == 0) {
        #pragma unroll
        for (int m = 0; m < 8; m++) {
            const float4 r0v = *(const float4*)&red[0][m][4 * c];
            const float4 r1v = *(const float4*)&red[1][m][4 * c];
            const float4 r2v = *(const float4*)&red[2][m][4 * c];
            float4 a = acc[m];
            a.x += r0v.x + r1v.x + r2v.x;
            a.y += r0v.y + r1v.y + r2v.y;
            a.z += r0v.z + r1v.z + r2v.z;
            a.w += r0v.w + r1v.w + r2v.w;
            const int row = r0 + m;
            if (mat == 0) {
                *(float4*)&g_q[(size_t)row * HID + 4 * c] = a;
            } else if (mat == 1) {
                *(float4*)&g_k[(size_t)row * HID + 4 * c] = a;
            } else {
                const float4 pv = *(const float4*)&posV[(size_t)row * HID + 4 * c];
                a.x += pv.x; a.y += pv.y; a.z += pv.z; a.w += pv.w;
                *(float4*)&g_vpos[(size_t)row * HID + 4 * c] = a;
            }
        }
    }
}

// ---------------------------------------------------------------------------
// Kernel 1b: kpos = k + posK; order/dist scalar dot tables. 8 rows/block.
// ---------------------------------------------------------------------------
__global__ __launch_bounds__(256) void post_kernel(
    const float* __restrict__ posK,
    const float* __restrict__ order_w, const float* __restrict__ dist_w)
{
    const int f  = threadIdx.x;
    const int r0 = blockIdx.x * 8;

    __shared__ float qs[8][HID];
    __shared__ float ks[8][HID];

    #pragma unroll
    for (int m = 0; m < 8; m++) {
        const int row = r0 + m;
        const float kv = g_k[(size_t)row * HID + f];
        qs[m][f] = g_q[(size_t)row * HID + f];
        ks[m][f] = kv;
        g_kpos[(size_t)row * HID + f] = kv + posK[(size_t)row * HID + f];
    }
    __syncthreads();

    const int w = f >> 5, l = f & 31;
    const int row = r0 + w;
    const int b = row / SS, sidx = row % SS;
    #pragma unroll
    for (int h = 0; h < HH; h++) {
        float qo = qs[w][h*64 + l] * order_w[l]      + qs[w][h*64 + 32 + l] * order_w[32 + l];
        float qd = qs[w][h*64 + l] * dist_w[l]       + qs[w][h*64 + 32 + l] * dist_w[32 + l];
        float ko = ks[w][h*64 + l] * order_w[64 + l] + ks[w][h*64 + 32 + l] * order_w[96 + l];
        float kd = ks[w][h*64 + l] * dist_w[64 + l]  + ks[w][h*64 + 32 + l] * dist_w[96 + l];
        #pragma unroll
        for (int off = 16; off; off >>= 1) {
            qo += __shfl_xor_sync(0xffffffffu, qo, off);
            qd += __shfl_xor_sync(0xffffffffu, qd, off);
            ko += __shfl_xor_sync(0xffffffffu, ko, off);
            kd += __shfl_xor_sync(0xffffffffu, kd, off);
        }
        if (l == 0) {
            const int idx = (b * HH + h) * SS + sidx;
            g_qo[idx] = qo; g_qd[idx] = qd; g_ko[idx] = ko; g_kd[idx] = kd;
        }
    }
}

// ---------------------------------------------------------------------------
// Kernel 2a: scores + softmax. ITA=2 rows/block, 256 threads, grid 800.
// (round-7 proven version: kpos loads kept in-loop — they supply MLP)
// ---------------------------------------------------------------------------
#define ITA 2
__global__ __launch_bounds__(256) void score_kernel(
    const float* __restrict__ timeK,
    const float* __restrict__ mask,
    const float* __restrict__ p_order_b, const float* __restrict__ p_dist_b,
    const float* __restrict__ p_scalar)
{
    const int tid = threadIdx.x;
    const int blk = blockIdx.x;
    const int b  = blk / (SS / ITA);
    const int i0 = (blk % (SS / ITA)) * ITA;
    const int w = tid >> 5, l = tid & 31;

    __shared__ float sc[ITA][HH][SS];
    __shared__ float q_sh[ITA][HID];
    __shared__ float qos[ITA][HH], qds[ITA][HH];
    __shared__ float inv_s[ITA][HH];
    __shared__ float dl[SS];

    #pragma unroll
    for (int it = 0; it < ITA; it++)
        q_sh[it][tid] = g_q[((size_t)(b * SS + i0 + it)) * HID + tid];
    if (tid < ITA * HH) {
        const int it = tid >> 2, h = tid & 3;
        qos[it][h] = g_qo[(b * HH + h) * SS + i0 + it];
        qds[it][h] = g_qd[(b * HH + h) * SS + i0 + it];
    }
    if (tid < SS) dl[tid] = __logf((float)tid + 1.f);
    __syncthreads();

    float4 q0[ITA], q1[ITA];
    #pragma unroll
    for (int it = 0; it < ITA; it++) {
        q0[it] = *(const float4*)&q_sh[it][l * 8];
        q1[it] = *(const float4*)&q_sh[it][l * 8 + 4];
    }
    const int hh = l >> 3;

    const float* tk0 = timeK + ((size_t)(b * SS + i0))     * SS * HID;
    const float* tk1 = timeK + ((size_t)(b * SS + i0 + 1)) * SS * HID;
    const float* kpb = g_kpos + (size_t)b * SS * HID;

    // ---- phase 1: raw scores ----
    for (int j = w; j < SS; j += 8) {
        const float4* kp  = (const float4*)(kpb + (size_t)j * HID);
        const float4* ta0 = (const float4*)(tk0 + (size_t)j * HID);
        const float4* ta1 = (const float4*)(tk1 + (size_t)j * HID);
        const float4 k0 = kp[2 * l],  k1 = kp[2 * l + 1];
        const float4 a0 = ta0[2 * l], a1 = ta0[2 * l + 1];
        const float4 b0 = ta1[2 * l], b1 = ta1[2 * l + 1];

        float p0 = q0[0].x * (a0.x + k0.x) + q0[0].y * (a0.y + k0.y)
                 + q0[0].z * (a0.z + k0.z) + q0[0].w * (a0.w + k0.w)
                 + q1[0].x * (a1.x + k1.x) + q1[0].y * (a1.y + k1.y)
                 + q1[0].z * (a1.z + k1.z) + q1[0].w * (a1.w + k1.w);
        float p1 = q0[1].x * (b0.x + k0.x) + q0[1].y * (b0.y + k0.y)
                 + q0[1].z * (b0.z + k0.z) + q0[1].w * (b0.w + k0.w)
                 + q1[1].x * (b1.x + k1.x) + q1[1].y * (b1.y + k1.y)
                 + q1[1].z * (b1.z + k1.z) + q1[1].w * (b1.w + k1.w);
        p0 += __shfl_xor_sync(0xffffffffu, p0, 1);
        p0 += __shfl_xor_sync(0xffffffffu, p0, 2);
        p0 += __shfl_xor_sync(0xffffffffu, p0, 4);
        p1 += __shfl_xor_sync(0xffffffffu, p1, 1);
        p1 += __shfl_xor_sync(0xffffffffu, p1, 2);
        p1 += __shfl_xor_sync(0xffffffffu, p1, 4);
        if ((l & 7) == 0) { sc[0][hh][j] = p0; sc[1][hh][j] = p1; }
    }
    __syncthreads();

    // ---- phase 2: order/dist error terms, scale, mask ----
    const float order_b = *p_order_b;
    const float dist_b  = *p_dist_b;
    const float sc2 = p_scalar[0] * p_scalar[0] * 0.5f;
    for (int idx = tid; idx < ITA * HH * SS; idx += 256) {
        const int it = idx / (HH * SS);
        const int rem = idx - it * (HH * SS);
        const int h = rem / SS, j = rem - (rem / SS) * SS;
        const int i = i0 + it;
        const float z = qos[it][h] + g_ko[(b * HH + h) * SS + j] + order_b;
        const float zz = (j > i) ? -z : z;     // log-sigmoid via softplus
        const float eo = -(fmaxf(zz, 0.f) + __logf(1.f + __expf(-fabsf(zz))));
        const float gd = dl[abs(j - i)];
        const float pd = qds[it][h] + g_kd[(b * HH + h) * SS + j] + dist_b;
        const float ed = -(gd - pd) * (gd - pd) * sc2;
        sc[it][h][j] = (sc[it][h][j] + eo + ed) * 0.125f
                     + mask[((size_t)b * SS + i) * SS + j];
    }
    __syncthreads();

    // ---- phase 3: softmax (warp per (it,h) pair; 8 warps = 8 pairs) ----
    {
        const int it = w >> 2, h = w & 3;
        float m = -1e30f;
        for (int j = l; j < SS; j += 32) m = fmaxf(m, sc[it][h][j]);
        #pragma unroll
        for (int off = 16; off; off >>= 1)
            m = fmaxf(m, __shfl_xor_sync(0xffffffffu, m, off));
        float sum = 0.f;
        for (int j = l; j < SS; j += 32) {
            const float e = __expf(sc[it][h][j] - m);
            sc[it][h][j] = e;
            sum += e;
        }
        #pragma unroll
        for (int off = 16; off; off >>= 1)
            sum += __shfl_xor_sync(0xffffffffu, sum, off);
        if (l == 0) inv_s[it][h] = 1.f / sum;
    }
    __syncthreads();

    // ---- write normalized probs ----
    for (int idx = tid; idx < ITA * HH * SS; idx += 256) {
        const int it = idx / (HH * SS);
        const int rem = idx - it * (HH * SS);
        const int h = rem / SS, j = rem - (rem / SS) * SS;
        g_probs[((size_t)(b * SS + i0 + it) * HH + h) * SS + j]
            = sc[it][h][j] * inv_s[it][h];
    }
}

// ---------------------------------------------------------------------------
// Kernel 2b: ctx accumulation. ONE i-row per block, split-j x4, 256 threads,
// grid 1600 (kills wave-quantization tail). vpos kept in-loop (free MLP).
// ---------------------------------------------------------------------------
__global__ __launch_bounds__(256) void ctx_kernel(
    const float* __restrict__ timeV)
{
    const int tid = threadIdx.x;
    const int blk = blockIdx.x;
    const int b = blk / SS, i = blk % SS;

    const int grp = tid >> 6;         // j-quarter 0..3 (50 j each)
    const int fq  = tid & 63;         // float4 index; f = 4*fq
    const int h   = fq >> 4;          // head of this f-quad

    __shared__ float pr[HH * SS];      // 3.2KB
    __shared__ float4 part[3][64];     // 3KB partials from grps 1..3

    for (int t = tid; t < HH * SS; t += 256)
        pr[t] = g_probs[((size_t)(b * SS + i) * HH) * SS + t];
    __syncthreads();

    const float4* tv = (const float4*)(timeV + ((size_t)(b * SS + i)) * SS * HID) + fq;
    const float4* vp = (const float4*)(g_vpos + (size_t)b * SS * HID) + fq;
    const float* prow = &pr[h * SS];

    const int j0 = grp * (SS / 4);
    float4 acc = make_float4(0.f, 0.f, 0.f, 0.f);
    #pragma unroll 5
    for (int j = j0; j < j0 + SS / 4; j++) {
        const float p = prow[j];
        const float4 t4 = tv[(size_t)j * (HID / 4)];
        const float4 v4 = vp[(size_t)j * (HID / 4)];
        acc.x += p * (t4.x + v4.x);
        acc.y += p * (t4.y + v4.y);
        acc.z += p * (t4.z + v4.z);
        acc.w += p * (t4.w + v4.w);
    }

    if (grp > 0) part[grp - 1][fq] = acc;
    __syncthreads();
    if (grp == 0) {
        #pragma unroll
        for (int g = 0; g < 3; g++) {
            const float4 p4 = part[g][fq];
            acc.x += p4.x; acc.y += p4.y; acc.z += p4.z; acc.w += p4.w;
        }
        *(float4*)&g_ctx[((size_t)(b * SS + i)) * HID + 4 * fq] = acc;
    }
}

// ---------------------------------------------------------------------------
// Kernel 3: output projection, 4 rows/block (grid 400) + residual + LN.
// ---------------------------------------------------------------------------
__global__ __launch_bounds__(256) void outln_kernel(
    const float* __restrict__ x,
    const float* __restrict__ Wd, const float* __restrict__ bd,
    const float* __restrict__ ln_g, const float* __restrict__ ln_b,
    float* __restrict__ out)
{
    const int r0  = blockIdx.x * 4;
    const int tid = threadIdx.x;
    const int s   = tid >> 6;
    const int c   = tid & 63;

    __shared__ float cs[HID][4];
    __shared__ float red[3][4][HID];
    __shared__ float hsm[4][HID];
    __shared__ float mu[4], rstd[4];

    for (int t = tid; t < 4 * HID; t += 256) {
        const int m = t >> 8, g = t & 255;
        cs[g][m] = g_ctx[(size_t)(r0 + m) * HID + g];
    }
    __syncthreads();

    float4 acc[4];
    if (s == 0) {
        const float4 b4 = *(const float4*)&bd[4 * c];
        #pragma unroll
        for (int m = 0; m < 4; m++) acc[m] = b4;
    } else {
        #pragma unroll
        for (int m = 0; m < 4; m++) acc[m] = make_float4(0.f, 0.f, 0.f, 0.f);
    }

    const float* __restrict__ Wp = Wd + (size_t)(s * 64) * HID + 4 * c;
    const float* __restrict__ xp = &cs[s * 64][0];
    #pragma unroll 4
    for (int gi = 0; gi < 64; gi++) {
        const float4 w = *(const float4*)(Wp + (size_t)gi * HID);
        #pragma unroll
        for (int m = 0; m < 4; m++) {
            const float xv = xp[gi * 4 + m];
            acc[m].x += xv * w.x; acc[m].y += xv * w.y;
            acc[m].z += xv * w.z; acc[m].w += xv * w.w;
        }
    }

    if (s > 0) {
        #pragma unroll
        for (int m = 0; m < 4; m++)
            *(float4*)&red[s - 1][m][4 * c] = acc[m];
    }
    __syncthreads();

    if (s == 0) {
        #pragma unroll
        for (int m = 0; m < 4; m++) {
            const float4 p0 = *(const float4*)&red[0][m][4 * c];
            const float4 p1 = *(const float4*)&red[1][m][4 * c];
            const float4 p2 = *(const float4*)&red[2][m][4 * c];
            const float4 xv = *(const float4*)&x[(size_t)(r0 + m) * HID + 4 * c];
            float4 a = acc[m];
            a.x += p0.x + p1.x + p2.x + xv.x;
            a.y += p0.y + p1.y + p2.y + xv.y;
            a.z += p0.z + p1.z + p2.z + xv.z;
            a.w += p0.w + p1.w + p2.w + xv.w;
            *(float4*)&hsm[m][4 * c] = a;
        }
    }
    __syncthreads();

    const int w = tid >> 5, l = tid & 31;
    if (w < 4) {
        float sum = 0.f, sum2 = 0.f;
        #pragma unroll
        for (int t = 0; t < 8; t++) {
            const float v = hsm[w][l + 32 * t];
            sum += v; sum2 += v * v;
        }
        #pragma unroll
        for (int off = 16; off; off >>= 1) {
            sum  += __shfl_xor_sync(0xffffffffu, sum,  off);
            sum2 += __shfl_xor_sync(0xffffffffu, sum2, off);
        }
        if (l == 0) {
            const float m_  = sum / HID;
            const float var = sum2 / HID - m_ * m_;
            mu[w]   = m_;
            rstd[w] = rsqrtf(var + 1e-12f);
        }
    }
    __syncthreads();

    const int f = tid;
    const float gf = ln_g[f], bf = ln_b[f];
    #pragma unroll
    for (int m = 0; m < 4; m++)
        out[(size_t)(r0 + m) * HID + f] = (hsm[m][f] - mu[m]) * rstd[m] * gf + bf;
}

// ---------------------------------------------------------------------------
extern "C" void kernel_launch(void* const* d_in, const int* in_sizes, int n_in,
                              void* d_out, int out_size)
{
    const float* x     = (const float*)d_in[0];
    const float* mask  = (const float*)d_in[1];
    const float* posK  = (const float*)d_in[2];
    const float* posV  = (const float*)d_in[3];
    const float* timeK = (const float*)d_in[4];
    const float* timeV = (const float*)d_in[5];
    const float* Wq = (const float*)d_in[6];  const float* bq = (const float*)d_in[7];
    const float* Wk = (const float*)d_in[8];  const float* bk = (const float*)d_in[9];
    const float* Wv = (const float*)d_in[10]; const float* bv = (const float*)d_in[11];
    const float* ow = (const float*)d_in[12]; const float* ob = (const float*)d_in[13];
    const float* dw = (const float*)d_in[14]; const float* db = (const float*)d_in[15];
    const float* sca = (const float*)d_in[16];
    const float* Wd = (const float*)d_in[17]; const float* bd = (const float*)d_in[18];
    const float* lg = (const float*)d_in[19]; const float* lb = (const float*)d_in[20];

    dim3 g1(NBS / 8, 3);
    gemm3_kernel<<<g1, 256>>>(x, Wq, bq, Wk, bk, Wv, bv, posV);
    post_kernel<<<NBS / 8, 256>>>(posK, ow, dw);
    score_kernel<<<NBS / ITA, 256>>>(timeK, mask, ob, db, sca);
    ctx_kernel<<<NBS, 256>>>(timeV);
    outln_kernel<<<NBS / 4, 256>>>(x, Wd, bd, lg, lb, (float*)d_out);
}

// round 10
// speedup vs baseline: 1.4384x; 1.0570x over previous
#include <cuda_runtime.h>
#include <math.h>

#define BB 8
#define SS 200
#define HH 4
#define DD 64
#define HID 256
#define NBS (BB*SS)   // 1600

// scratch (device globals; no allocation allowed)
__device__ float g_q[NBS*HID];
__device__ float g_k[NBS*HID];
__device__ float g_kpos[NBS*HID];
__device__ float g_vpos[NBS*HID];
__device__ float g_qo[BB*HH*SS];
__device__ float g_ko[BB*HH*SS];
__device__ float g_qd[BB*HH*SS];
__device__ float g_kd[BB*HH*SS];
__device__ float g_probs[NBS*HH*SS];   // normalized probs, [b][i][h][j]
__device__ float g_ctx[NBS*HID];

// ---------------------------------------------------------------------------
// Kernel 1: one (8-row, matrix) tile per block; split-K x4 inside the block.
// ---------------------------------------------------------------------------
__global__ __launch_bounds__(256) void gemm3_kernel(
    const float* __restrict__ x,
    const float* __restrict__ Wq, const float* __restrict__ bq,
    const float* __restrict__ Wk, const float* __restrict__ bk,
    const float* __restrict__ Wv, const float* __restrict__ bv,
    const float* __restrict__ posV)
{
    const int r0  = blockIdx.x * 8;
    const int mat = blockIdx.y;
    const float* __restrict__ W    = (mat == 0) ? Wq : (mat == 1) ? Wk : Wv;
    const float* __restrict__ bias = (mat == 0) ? bq : (mat == 1) ? bk : bv;

    const int tid = threadIdx.x;
    const int s   = tid >> 6;
    const int c   = tid & 63;

    __shared__ float xs[HID][8];
    __shared__ float red[3][8][HID];

    for (int t = tid; t < 8 * HID; t += 256) {
        const int m = t >> 8, g = t & 255;
        xs[g][m] = x[(r0 + m) * HID + g];
    }
    __syncthreads();

    float4 acc[8];
    if (s == 0) {
        const float4 b4 = *(const float4*)&bias[4 * c];
        #pragma unroll
        for (int m = 0; m < 8; m++) acc[m] = b4;
    } else {
        #pragma unroll
        for (int m = 0; m < 8; m++) acc[m] = make_float4(0.f, 0.f, 0.f, 0.f);
    }

    const float* __restrict__ Wp = W + (size_t)(s * 64) * HID + 4 * c;
    const float* __restrict__ xp = &xs[s * 64][0];
    #pragma unroll 4
    for (int gi = 0; gi < 64; gi++) {
        const float4 w = *(const float4*)(Wp + (size_t)gi * HID);
        #pragma unroll
        for (int m = 0; m < 8; m++) {
            const float xv = xp[gi * 8 + m];
            acc[m].x += xv * w.x; acc[m].y += xv * w.y;
            acc[m].z += xv * w.z; acc[m].w += xv * w.w;
        }
    }

    if (s > 0) {
        #pragma unroll
        for (int m = 0; m < 8; m++)
            *(float4*)&red[s - 1][m][4 * c] = acc[m];
    }
    __syncthreads();

    if (s == 0) {
        #pragma unroll
        for (int m = 0; m < 8; m++) {
            const float4 r0v = *(const float4*)&red[0][m][4 * c];
            const float4 r1v = *(const float4*)&red[1][m][4 * c];
            const float4 r2v = *(const float4*)&red[2][m][4 * c];
            float4 a = acc[m];
            a.x += r0v.x + r1v.x + r2v.x;
            a.y += r0v.y + r1v.y + r2v.y;
            a.z += r0v.z + r1v.z + r2v.z;
            a.w += r0v.w + r1v.w + r2v.w;
            const int row = r0 + m;
            if (mat == 0) {
                *(float4*)&g_q[(size_t)row * HID + 4 * c] = a;
            } else if (mat == 1) {
                *(float4*)&g_k[(size_t)row * HID + 4 * c] = a;
            } else {
                const float4 pv = *(const float4*)&posV[(size_t)row * HID + 4 * c];
                a.x += pv.x; a.y += pv.y; a.z += pv.z; a.w += pv.w;
                *(float4*)&g_vpos[(size_t)row * HID + 4 * c] = a;
            }
        }
    }
}

// ---------------------------------------------------------------------------
// Kernel 1b: kpos = k + posK; order/dist scalar dot tables. 8 rows/block.
// ---------------------------------------------------------------------------
__global__ __launch_bounds__(256) void post_kernel(
    const float* __restrict__ posK,
    const float* __restrict__ order_w, const float* __restrict__ dist_w)
{
    const int f  = threadIdx.x;
    const int r0 = blockIdx.x * 8;

    __shared__ float qs[8][HID];
    __shared__ float ks[8][HID];

    #pragma unroll
    for (int m = 0; m < 8; m++) {
        const int row = r0 + m;
        const float kv = g_k[(size_t)row * HID + f];
        qs[m][f] = g_q[(size_t)row * HID + f];
        ks[m][f] = kv;
        g_kpos[(size_t)row * HID + f] = kv + posK[(size_t)row * HID + f];
    }
    __syncthreads();

    const int w = f >> 5, l = f & 31;
    const int row = r0 + w;
    const int b = row / SS, sidx = row % SS;
    #pragma unroll
    for (int h = 0; h < HH; h++) {
        float qo = qs[w][h*64 + l] * order_w[l]      + qs[w][h*64 + 32 + l] * order_w[32 + l];
        float qd = qs[w][h*64 + l] * dist_w[l]       + qs[w][h*64 + 32 + l] * dist_w[32 + l];
        float ko = ks[w][h*64 + l] * order_w[64 + l] + ks[w][h*64 + 32 + l] * order_w[96 + l];
        float kd = ks[w][h*64 + l] * dist_w[64 + l]  + ks[w][h*64 + 32 + l] * dist_w[96 + l];
        #pragma unroll
        for (int off = 16; off; off >>= 1) {
            qo += __shfl_xor_sync(0xffffffffu, qo, off);
            qd += __shfl_xor_sync(0xffffffffu, qd, off);
            ko += __shfl_xor_sync(0xffffffffu, ko, off);
            kd += __shfl_xor_sync(0xffffffffu, kd, off);
        }
        if (l == 0) {
            const int idx = (b * HH + h) * SS + sidx;
            g_qo[idx] = qo; g_qd[idx] = qd; g_ko[idx] = ko; g_kd[idx] = kd;
        }
    }
}

// ---------------------------------------------------------------------------
// Kernel 2a: scores + softmax. ONE i-row per block (grid 1600), 256 threads.
// ctx-style small-block recipe; kpos in-loop (L2-hit loads = free MLP).
// ---------------------------------------------------------------------------
__global__ __launch_bounds__(256) void score_kernel(
    const float* __restrict__ timeK,
    const float* __restrict__ mask,
    const float* __restrict__ p_order_b, const float* __restrict__ p_dist_b,
    const float* __restrict__ p_scalar)
{
    const int tid = threadIdx.x;
    const int blk = blockIdx.x;
    const int b = blk / SS, i = blk % SS;
    const int w = tid >> 5, l = tid & 31;

    __shared__ float sc[HH][SS];       // 3.2KB: scores -> exp
    __shared__ float q_sh[HID];        // 1KB
    __shared__ float qos[HH], qds[HH];
    __shared__ float inv_s[HH];
    __shared__ float dl[SS];           // log(|d|+1) table

    q_sh[tid] = g_q[((size_t)(b * SS + i)) * HID + tid];
    if (tid < HH) {
        qos[tid] = g_qo[(b * HH + tid) * SS + i];
        qds[tid] = g_qd[(b * HH + tid) * SS + i];
    }
    if (tid < SS) dl[tid] = __logf((float)tid + 1.f);
    __syncthreads();

    // per-lane fixed q slice: floats [8l, 8l+8)
    const float4 q0 = *(const float4*)&q_sh[l * 8];
    const float4 q1 = *(const float4*)&q_sh[l * 8 + 4];
    const int hh = l >> 3;

    const float* tkb = timeK + ((size_t)(b * SS + i)) * SS * HID;
    const float* kpb = g_kpos + (size_t)b * SS * HID;

    // ---- phase 1: raw scores  q . (timeK_ij + kpos_j) ----
    for (int j = w; j < SS; j += 8) {
        const float4* kp = (const float4*)(kpb + (size_t)j * HID);
        const float4* tk = (const float4*)(tkb + (size_t)j * HID);
        const float4 k0 = kp[2 * l], k1 = kp[2 * l + 1];
        const float4 t0 = tk[2 * l], t1 = tk[2 * l + 1];
        float p = q0.x * (t0.x + k0.x) + q0.y * (t0.y + k0.y)
                + q0.z * (t0.z + k0.z) + q0.w * (t0.w + k0.w)
                + q1.x * (t1.x + k1.x) + q1.y * (t1.y + k1.y)
                + q1.z * (t1.z + k1.z) + q1.w * (t1.w + k1.w);
        p += __shfl_xor_sync(0xffffffffu, p, 1);
        p += __shfl_xor_sync(0xffffffffu, p, 2);
        p += __shfl_xor_sync(0xffffffffu, p, 4);
        if ((l & 7) == 0) sc[hh][j] = p;
    }
    __syncthreads();

    // ---- phase 2: order/dist error terms, scale, mask ----
    const float order_b = *p_order_b;
    const float dist_b  = *p_dist_b;
    const float sc2 = p_scalar[0] * p_scalar[0] * 0.5f;
    for (int idx = tid; idx < HH * SS; idx += 256) {
        const int h = idx / SS, j = idx - (idx / SS) * SS;
        const float z = qos[h] + g_ko[(b * HH + h) * SS + j] + order_b;
        const float zz = (j > i) ? -z : z;     // log-sigmoid via softplus
        const float eo = -(fmaxf(zz, 0.f) + __logf(1.f + __expf(-fabsf(zz))));
        const float gd = dl[abs(j - i)];
        const float pd = qds[h] + g_kd[(b * HH + h) * SS + j] + dist_b;
        const float ed = -(gd - pd) * (gd - pd) * sc2;
        sc[h][j] = (sc[h][j] + eo + ed) * 0.125f
                 + mask[((size_t)b * SS + i) * SS + j];
    }
    __syncthreads();

    // ---- phase 3: softmax (warp h handles head h) ----
    if (w < HH) {
        float m = -1e30f;
        for (int j = l; j < SS; j += 32) m = fmaxf(m, sc[w][j]);
        #pragma unroll
        for (int off = 16; off; off >>= 1)
            m = fmaxf(m, __shfl_xor_sync(0xffffffffu, m, off));
        float sum = 0.f;
        for (int j = l; j < SS; j += 32) {
            const float e = __expf(sc[w][j] - m);
            sc[w][j] = e;
            sum += e;
        }
        #pragma unroll
        for (int off = 16; off; off >>= 1)
            sum += __shfl_xor_sync(0xffffffffu, sum, off);
        if (l == 0) inv_s[w] = 1.f / sum;
    }
    __syncthreads();

    // ---- write normalized probs ----
    for (int idx = tid; idx < HH * SS; idx += 256) {
        const int h = idx / SS, j = idx - (idx / SS) * SS;
        g_probs[((size_t)(b * SS + i) * HH + h) * SS + j] = sc[h][j] * inv_s[h];
    }
}

// ---------------------------------------------------------------------------
// Kernel 2b: ctx accumulation. ONE i-row per block, split-j x4, 256 threads,
// grid 1600. vpos kept in-loop (free MLP).
// ---------------------------------------------------------------------------
__global__ __launch_bounds__(256) void ctx_kernel(
    const float* __restrict__ timeV)
{
    const int tid = threadIdx.x;
    const int blk = blockIdx.x;
    const int b = blk / SS, i = blk % SS;

    const int grp = tid >> 6;         // j-quarter 0..3 (50 j each)
    const int fq  = tid & 63;         // float4 index; f = 4*fq
    const int h   = fq >> 4;          // head of this f-quad

    __shared__ float pr[HH * SS];      // 3.2KB
    __shared__ float4 part[3][64];     // 3KB partials from grps 1..3

    for (int t = tid; t < HH * SS; t += 256)
        pr[t] = g_probs[((size_t)(b * SS + i) * HH) * SS + t];
    __syncthreads();

    const float4* tv = (const float4*)(timeV + ((size_t)(b * SS + i)) * SS * HID) + fq;
    const float4* vp = (const float4*)(g_vpos + (size_t)b * SS * HID) + fq;
    const float* prow = &pr[h * SS];

    const int j0 = grp * (SS / 4);
    float4 acc = make_float4(0.f, 0.f, 0.f, 0.f);
    #pragma unroll 5
    for (int j = j0; j < j0 + SS / 4; j++) {
        const float p = prow[j];
        const float4 t4 = tv[(size_t)j * (HID / 4)];
        const float4 v4 = vp[(size_t)j * (HID / 4)];
        acc.x += p * (t4.x + v4.x);
        acc.y += p * (t4.y + v4.y);
        acc.z += p * (t4.z + v4.z);
        acc.w += p * (t4.w + v4.w);
    }

    if (grp > 0) part[grp - 1][fq] = acc;
    __syncthreads();
    if (grp == 0) {
        #pragma unroll
        for (int g = 0; g < 3; g++) {
            const float4 p4 = part[g][fq];
            acc.x += p4.x; acc.y += p4.y; acc.z += p4.z; acc.w += p4.w;
        }
        *(float4*)&g_ctx[((size_t)(b * SS + i)) * HID + 4 * fq] = acc;
    }
}

// ---------------------------------------------------------------------------
// Kernel 3: output projection, 4 rows/block (grid 400) + residual + LN.
// ---------------------------------------------------------------------------
__global__ __launch_bounds__(256) void outln_kernel(
    const float* __restrict__ x,
    const float* __restrict__ Wd, const float* __restrict__ bd,
    const float* __restrict__ ln_g, const float* __restrict__ ln_b,
    float* __restrict__ out)
{
    const int r0  = blockIdx.x * 4;
    const int tid = threadIdx.x;
    const int s   = tid >> 6;
    const int c   = tid & 63;

    __shared__ float cs[HID][4];
    __shared__ float red[3][4][HID];
    __shared__ float hsm[4][HID];
    __shared__ float mu[4], rstd[4];

    for (int t = tid; t < 4 * HID; t += 256) {
        const int m = t >> 8, g = t & 255;
        cs[g][m] = g_ctx[(size_t)(r0 + m) * HID + g];
    }
    __syncthreads();

    float4 acc[4];
    if (s == 0) {
        const float4 b4 = *(const float4*)&bd[4 * c];
        #pragma unroll
        for (int m = 0; m < 4; m++) acc[m] = b4;
    } else {
        #pragma unroll
        for (int m = 0; m < 4; m++) acc[m] = make_float4(0.f, 0.f, 0.f, 0.f);
    }

    const float* __restrict__ Wp = Wd + (size_t)(s * 64) * HID + 4 * c;
    const float* __restrict__ xp = &cs[s * 64][0];
    #pragma unroll 4
    for (int gi = 0; gi < 64; gi++) {
        const float4 w = *(const float4*)(Wp + (size_t)gi * HID);
        #pragma unroll
        for (int m = 0; m < 4; m++) {
            const float xv = xp[gi * 4 + m];
            acc[m].x += xv * w.x; acc[m].y += xv * w.y;
            acc[m].z += xv * w.z; acc[m].w += xv * w.w;
        }
    }

    if (s > 0) {
        #pragma unroll
        for (int m = 0; m < 4; m++)
            *(float4*)&red[s - 1][m][4 * c] = acc[m];
    }
    __syncthreads();

    if (s == 0) {
        #pragma unroll
        for (int m = 0; m < 4; m++) {
            const float4 p0 = *(const float4*)&red[0][m][4 * c];
            const float4 p1 = *(const float4*)&red[1][m][4 * c];
            const float4 p2 = *(const float4*)&red[2][m][4 * c];
            const float4 xv = *(const float4*)&x[(size_t)(r0 + m) * HID + 4 * c];
            float4 a = acc[m];
            a.x += p0.x + p1.x + p2.x + xv.x;
            a.y += p0.y + p1.y + p2.y + xv.y;
            a.z += p0.z + p1.z + p2.z + xv.z;
            a.w += p0.w + p1.w + p2.w + xv.w;
            *(float4*)&hsm[m][4 * c] = a;
        }
    }
    __syncthreads();

    const int w = tid >> 5, l = tid & 31;
    if (w < 4) {
        float sum = 0.f, sum2 = 0.f;
        #pragma unroll
        for (int t = 0; t < 8; t++) {
            const float v = hsm[w][l + 32 * t];
            sum += v; sum2 += v * v;
        }
        #pragma unroll
        for (int off = 16; off; off >>= 1) {
            sum  += __shfl_xor_sync(0xffffffffu, sum,  off);
            sum2 += __shfl_xor_sync(0xffffffffu, sum2, off);
        }
        if (l == 0) {
            const float m_  = sum / HID;
            const float var = sum2 / HID - m_ * m_;
            mu[w]   = m_;
            rstd[w] = rsqrtf(var + 1e-12f);
        }
    }
    __syncthreads();

    const int f = tid;
    const float gf = ln_g[f], bf = ln_b[f];
    #pragma unroll
    for (int m = 0; m < 4; m++)
        out[(size_t)(r0 + m) * HID + f] = (hsm[m][f] - mu[m]) * rstd[m] * gf + bf;
}

// ---------------------------------------------------------------------------
extern "C" void kernel_launch(void* const* d_in, const int* in_sizes, int n_in,
                              void* d_out, int out_size)
{
    const float* x     = (const float*)d_in[0];
    const float* mask  = (const float*)d_in[1];
    const float* posK  = (const float*)d_in[2];
    const float* posV  = (const float*)d_in[3];
    const float* timeK = (const float*)d_in[4];
    const float* timeV = (const float*)d_in[5];
    const float* Wq = (const float*)d_in[6];  const float* bq = (const float*)d_in[7];
    const float* Wk = (const float*)d_in[8];  const float* bk = (const float*)d_in[9];
    const float* Wv = (const float*)d_in[10]; const float* bv = (const float*)d_in[11];
    const float* ow = (const float*)d_in[12]; const float* ob = (const float*)d_in[13];
    const float* dw = (const float*)d_in[14]; const float* db = (const float*)d_in[15];
    const float* sca = (const float*)d_in[16];
    const float* Wd = (const float*)d_in[17]; const float* bd = (const float*)d_in[18];
    const float* lg = (const float*)d_in[19]; const float* lb = (const float*)d_in[20];

    dim3 g1(NBS / 8, 3);
    gemm3_kernel<<<g1, 256>>>(x, Wq, bq, Wk, bk, Wv, bv, posV);
    post_kernel<<<NBS / 8, 256>>>(posK, ow, dw);
    score_kernel<<<NBS, 256>>>(timeK, mask, ob, db, sca);
    ctx_kernel<<<NBS, 256>>>(timeV);
    outln_kernel<<<NBS / 4, 256>>>(x, Wd, bd, lg, lb, (float*)d_out);
}

// round 11
// speedup vs baseline: 1.4443x; 1.0040x over previous
#include <cuda_runtime.h>
#include <math.h>

#define BB 8
#define SS 200
#define HH 4
#define DD 64
#define HID 256
#define NBS (BB*SS)   // 1600

// scratch (device globals; no allocation allowed)
__device__ float g_q[NBS*HID];
__device__ float g_k[NBS*HID];
__device__ float g_kpos[NBS*HID];
__device__ float g_vpos[NBS*HID];
__device__ float g_qo[BB*HH*SS];
__device__ float g_ko[BB*HH*SS];
__device__ float g_qd[BB*HH*SS];
__device__ float g_kd[BB*HH*SS];
__device__ float g_ctx[NBS*HID];

// ---------------------------------------------------------------------------
// Kernel 1: one (8-row, matrix) tile per block; split-K x4 inside the block.
// ---------------------------------------------------------------------------
__global__ __launch_bounds__(256) void gemm3_kernel(
    const float* __restrict__ x,
    const float* __restrict__ Wq, const float* __restrict__ bq,
    const float* __restrict__ Wk, const float* __restrict__ bk,
    const float* __restrict__ Wv, const float* __restrict__ bv,
    const float* __restrict__ posV)
{
    const int r0  = blockIdx.x * 8;
    const int mat = blockIdx.y;
    const float* __restrict__ W    = (mat == 0) ? Wq : (mat == 1) ? Wk : Wv;
    const float* __restrict__ bias = (mat == 0) ? bq : (mat == 1) ? bk : bv;

    const int tid = threadIdx.x;
    const int s   = tid >> 6;
    const int c   = tid & 63;

    __shared__ float xs[HID][8];
    __shared__ float red[3][8][HID];

    for (int t = tid; t < 8 * HID; t += 256) {
        const int m = t >> 8, g = t & 255;
        xs[g][m] = x[(r0 + m) * HID + g];
    }
    __syncthreads();

    float4 acc[8];
    if (s == 0) {
        const float4 b4 = *(const float4*)&bias[4 * c];
        #pragma unroll
        for (int m = 0; m < 8; m++) acc[m] = b4;
    } else {
        #pragma unroll
        for (int m = 0; m < 8; m++) acc[m] = make_float4(0.f, 0.f, 0.f, 0.f);
    }

    const float* __restrict__ Wp = W + (size_t)(s * 64) * HID + 4 * c;
    const float* __restrict__ xp = &xs[s * 64][0];
    #pragma unroll 4
    for (int gi = 0; gi < 64; gi++) {
        const float4 w = *(const float4*)(Wp + (size_t)gi * HID);
        #pragma unroll
        for (int m = 0; m < 8; m++) {
            const float xv = xp[gi * 8 + m];
            acc[m].x += xv * w.x; acc[m].y += xv * w.y;
            acc[m].z += xv * w.z; acc[m].w += xv * w.w;
        }
    }

    if (s > 0) {
        #pragma unroll
        for (int m = 0; m < 8; m++)
            *(float4*)&red[s - 1][m][4 * c] = acc[m];
    }
    __syncthreads();

    if (s == 0) {
        #pragma unroll
        for (int m = 0; m < 8; m++) {
            const float4 r0v = *(const float4*)&red[0][m][4 * c];
            const float4 r1v = *(const float4*)&red[1][m][4 * c];
            const float4 r2v = *(const float4*)&red[2][m][4 * c];
            float4 a = acc[m];
            a.x += r0v.x + r1v.x + r2v.x;
            a.y += r0v.y + r1v.y + r2v.y;
            a.z += r0v.z + r1v.z + r2v.z;
            a.w += r0v.w + r1v.w + r2v.w;
            const int row = r0 + m;
            if (mat == 0) {
                *(float4*)&g_q[(size_t)row * HID + 4 * c] = a;
            } else if (mat == 1) {
                *(float4*)&g_k[(size_t)row * HID + 4 * c] = a;
            } else {
                const float4 pv = *(const float4*)&posV[(size_t)row * HID + 4 * c];
                a.x += pv.x; a.y += pv.y; a.z += pv.z; a.w += pv.w;
                *(float4*)&g_vpos[(size_t)row * HID + 4 * c] = a;
            }
        }
    }
}

// ---------------------------------------------------------------------------
// Kernel 1b: kpos = k + posK; order/dist scalar dot tables. 8 rows/block.
// ---------------------------------------------------------------------------
__global__ __launch_bounds__(256) void post_kernel(
    const float* __restrict__ posK,
    const float* __restrict__ order_w, const float* __restrict__ dist_w)
{
    const int f  = threadIdx.x;
    const int r0 = blockIdx.x * 8;

    __shared__ float qs[8][HID];
    __shared__ float ks[8][HID];

    #pragma unroll
    for (int m = 0; m < 8; m++) {
        const int row = r0 + m;
        const float kv = g_k[(size_t)row * HID + f];
        qs[m][f] = g_q[(size_t)row * HID + f];
        ks[m][f] = kv;
        g_kpos[(size_t)row * HID + f] = kv + posK[(size_t)row * HID + f];
    }
    __syncthreads();

    const int w = f >> 5, l = f & 31;
    const int row = r0 + w;
    const int b = row / SS, sidx = row % SS;
    #pragma unroll
    for (int h = 0; h < HH; h++) {
        float qo = qs[w][h*64 + l] * order_w[l]      + qs[w][h*64 + 32 + l] * order_w[32 + l];
        float qd = qs[w][h*64 + l] * dist_w[l]       + qs[w][h*64 + 32 + l] * dist_w[32 + l];
        float ko = ks[w][h*64 + l] * order_w[64 + l] + ks[w][h*64 + 32 + l] * order_w[96 + l];
        float kd = ks[w][h*64 + l] * dist_w[64 + l]  + ks[w][h*64 + 32 + l] * dist_w[96 + l];
        #pragma unroll
        for (int off = 16; off; off >>= 1) {
            qo += __shfl_xor_sync(0xffffffffu, qo, off);
            qd += __shfl_xor_sync(0xffffffffu, qd, off);
            ko += __shfl_xor_sync(0xffffffffu, ko, off);
            kd += __shfl_xor_sync(0xffffffffu, kd, off);
        }
        if (l == 0) {
            const int idx = (b * HH + h) * SS + sidx;
            g_qo[idx] = qo; g_qd[idx] = qd; g_ko[idx] = ko; g_kd[idx] = kd;
        }
    }
}

// ---------------------------------------------------------------------------
// Kernel 2: FUSED scores + softmax + ctx. ONE i-row per block (grid 1600),
// 256 threads. Probs never leave shared memory; inv_s folded into the
// ctx epilogue scale. Streams timeK then timeV (staggered chip-wide).
// ---------------------------------------------------------------------------
__global__ __launch_bounds__(256) void attn_kernel(
    const float* __restrict__ timeK, const float* __restrict__ timeV,
    const float* __restrict__ mask,
    const float* __restrict__ p_order_b, const float* __restrict__ p_dist_b,
    const float* __restrict__ p_scalar)
{
    const int tid = threadIdx.x;
    const int blk = blockIdx.x;
    const int b = blk / SS, i = blk % SS;
    const int w = tid >> 5, l = tid & 31;

    __shared__ float sc[HH][SS];       // 3.2KB: scores -> exp (un-normalized)
    __shared__ float q_sh[HID];        // 1KB
    __shared__ float qos[HH], qds[HH];
    __shared__ float inv_s[HH];
    __shared__ float dl[SS];           // log(|d|+1) table
    __shared__ float4 part[3][64];     // 3KB ctx partials

    q_sh[tid] = g_q[((size_t)(b * SS + i)) * HID + tid];
    if (tid < HH) {
        qos[tid] = g_qo[(b * HH + tid) * SS + i];
        qds[tid] = g_qd[(b * HH + tid) * SS + i];
    }
    if (tid < SS) dl[tid] = __logf((float)tid + 1.f);
    __syncthreads();

    // per-lane fixed q slice: floats [8l, 8l+8)
    const float4 q0 = *(const float4*)&q_sh[l * 8];
    const float4 q1 = *(const float4*)&q_sh[l * 8 + 4];
    const int hh = l >> 3;

    const float* tkb = timeK + ((size_t)(b * SS + i)) * SS * HID;
    const float* kpb = g_kpos + (size_t)b * SS * HID;

    // ---- phase 1: raw scores  q . (timeK_ij + kpos_j) ----
    for (int j = w; j < SS; j += 8) {
        const float4* kp = (const float4*)(kpb + (size_t)j * HID);
        const float4* tk = (const float4*)(tkb + (size_t)j * HID);
        const float4 k0 = kp[2 * l], k1 = kp[2 * l + 1];
        const float4 t0 = tk[2 * l], t1 = tk[2 * l + 1];
        float p = q0.x * (t0.x + k0.x) + q0.y * (t0.y + k0.y)
                + q0.z * (t0.z + k0.z) + q0.w * (t0.w + k0.w)
                + q1.x * (t1.x + k1.x) + q1.y * (t1.y + k1.y)
                + q1.z * (t1.z + k1.z) + q1.w * (t1.w + k1.w);
        p += __shfl_xor_sync(0xffffffffu, p, 1);
        p += __shfl_xor_sync(0xffffffffu, p, 2);
        p += __shfl_xor_sync(0xffffffffu, p, 4);
        if ((l & 7) == 0) sc[hh][j] = p;
    }
    __syncthreads();

    // ---- phase 2: order/dist error terms, scale, mask ----
    const float order_b = *p_order_b;
    const float dist_b  = *p_dist_b;
    const float sc2 = p_scalar[0] * p_scalar[0] * 0.5f;
    for (int idx = tid; idx < HH * SS; idx += 256) {
        const int h = idx / SS, j = idx - (idx / SS) * SS;
        const float z = qos[h] + g_ko[(b * HH + h) * SS + j] + order_b;
        const float zz = (j > i) ? -z : z;     // log-sigmoid via softplus
        const float eo = -(fmaxf(zz, 0.f) + __logf(1.f + __expf(-fabsf(zz))));
        const float gd = dl[abs(j - i)];
        const float pd = qds[h] + g_kd[(b * HH + h) * SS + j] + dist_b;
        const float ed = -(gd - pd) * (gd - pd) * sc2;
        sc[h][j] = (sc[h][j] + eo + ed) * 0.125f
                 + mask[((size_t)b * SS + i) * SS + j];
    }
    __syncthreads();

    // ---- phase 3: softmax exp + sums (warp h handles head h) ----
    if (w < HH) {
        float m = -1e30f;
        for (int j = l; j < SS; j += 32) m = fmaxf(m, sc[w][j]);
        #pragma unroll
        for (int off = 16; off; off >>= 1)
            m = fmaxf(m, __shfl_xor_sync(0xffffffffu, m, off));
        float sum = 0.f;
        for (int j = l; j < SS; j += 32) {
            const float e = __expf(sc[w][j] - m);
            sc[w][j] = e;
            sum += e;
        }
        #pragma unroll
        for (int off = 16; off; off >>= 1)
            sum += __shfl_xor_sync(0xffffffffu, sum, off);
        if (l == 0) inv_s[w] = 1.f / sum;
    }
    __syncthreads();

    // ---- phase 4: ctx accumulation (split-j x4); inv_s folded at end ----
    {
        const int grp = tid >> 6;         // j-quarter 0..3 (50 j each)
        const int fq  = tid & 63;         // float4 index; f = 4*fq
        const int h   = fq >> 4;          // head of this f-quad

        const float4* tv = (const float4*)(timeV + ((size_t)(b * SS + i)) * SS * HID) + fq;
        const float4* vp = (const float4*)(g_vpos + (size_t)b * SS * HID) + fq;
        const float* prow = &sc[h][0];

        const int j0 = grp * (SS / 4);
        float4 acc = make_float4(0.f, 0.f, 0.f, 0.f);
        #pragma unroll 5
        for (int j = j0; j < j0 + SS / 4; j++) {
            const float p = prow[j];
            const float4 t4 = tv[(size_t)j * (HID / 4)];
            const float4 v4 = vp[(size_t)j * (HID / 4)];
            acc.x += p * (t4.x + v4.x);
            acc.y += p * (t4.y + v4.y);
            acc.z += p * (t4.z + v4.z);
            acc.w += p * (t4.w + v4.w);
        }

        if (grp > 0) part[grp - 1][fq] = acc;
        __syncthreads();
        if (grp == 0) {
            #pragma unroll
            for (int g = 0; g < 3; g++) {
                const float4 p4 = part[g][fq];
                acc.x += p4.x; acc.y += p4.y; acc.z += p4.z; acc.w += p4.w;
            }
            const float is = inv_s[h];
            acc.x *= is; acc.y *= is; acc.z *= is; acc.w *= is;
            *(float4*)&g_ctx[((size_t)(b * SS + i)) * HID + 4 * fq] = acc;
        }
    }
}

// ---------------------------------------------------------------------------
// Kernel 3: output projection, 4 rows/block (grid 400) + residual + LN.
// ---------------------------------------------------------------------------
__global__ __launch_bounds__(256) void outln_kernel(
    const float* __restrict__ x,
    const float* __restrict__ Wd, const float* __restrict__ bd,
    const float* __restrict__ ln_g, const float* __restrict__ ln_b,
    float* __restrict__ out)
{
    const int r0  = blockIdx.x * 4;
    const int tid = threadIdx.x;
    const int s   = tid >> 6;
    const int c   = tid & 63;

    __shared__ float cs[HID][4];
    __shared__ float red[3][4][HID];
    __shared__ float hsm[4][HID];
    __shared__ float mu[4], rstd[4];

    for (int t = tid; t < 4 * HID; t += 256) {
        const int m = t >> 8, g = t & 255;
        cs[g][m] = g_ctx[(size_t)(r0 + m) * HID + g];
    }
    __syncthreads();

    float4 acc[4];
    if (s == 0) {
        const float4 b4 = *(const float4*)&bd[4 * c];
        #pragma unroll
        for (int m = 0; m < 4; m++) acc[m] = b4;
    } else {
        #pragma unroll
        for (int m = 0; m < 4; m++) acc[m] = make_float4(0.f, 0.f, 0.f, 0.f);
    }

    const float* __restrict__ Wp = Wd + (size_t)(s * 64) * HID + 4 * c;
    const float* __restrict__ xp = &cs[s * 64][0];
    #pragma unroll 4
    for (int gi = 0; gi < 64; gi++) {
        const float4 w = *(const float4*)(Wp + (size_t)gi * HID);
        #pragma unroll
        for (int m = 0; m < 4; m++) {
            const float xv = xp[gi * 4 + m];
            acc[m].x += xv * w.x; acc[m].y += xv * w.y;
            acc[m].z += xv * w.z; acc[m].w += xv * w.w;
        }
    }

    if (s > 0) {
        #pragma unroll
        for (int m = 0; m < 4; m++)
            *(float4*)&red[s - 1][m][4 * c] = acc[m];
    }
    __syncthreads();

    if (s == 0) {
        #pragma unroll
        for (int m = 0; m < 4; m++) {
            const float4 p0 = *(const float4*)&red[0][m][4 * c];
            const float4 p1 = *(const float4*)&red[1][m][4 * c];
            const float4 p2 = *(const float4*)&red[2][m][4 * c];
            const float4 xv = *(const float4*)&x[(size_t)(r0 + m) * HID + 4 * c];
            float4 a = acc[m];
            a.x += p0.x + p1.x + p2.x + xv.x;
            a.y += p0.y + p1.y + p2.y + xv.y;
            a.z += p0.z + p1.z + p2.z + xv.z;
            a.w += p0.w + p1.w + p2.w + xv.w;
            *(float4*)&hsm[m][4 * c] = a;
        }
    }
    __syncthreads();

    const int w = tid >> 5, l = tid & 31;
    if (w < 4) {
        float sum = 0.f, sum2 = 0.f;
        #pragma unroll
        for (int t = 0; t < 8; t++) {
            const float v = hsm[w][l + 32 * t];
            sum += v; sum2 += v * v;
        }
        #pragma unroll
        for (int off = 16; off; off >>= 1) {
            sum  += __shfl_xor_sync(0xffffffffu, sum,  off);
            sum2 += __shfl_xor_sync(0xffffffffu, sum2, off);
        }
        if (l == 0) {
            const float m_  = sum / HID;
            const float var = sum2 / HID - m_ * m_;
            mu[w]   = m_;
            rstd[w] = rsqrtf(var + 1e-12f);
        }
    }
    __syncthreads();

    const int f = tid;
    const float gf = ln_g[f], bf = ln_b[f];
    #pragma unroll
    for (int m = 0; m < 4; m++)
        out[(size_t)(r0 + m) * HID + f] = (hsm[m][f] - mu[m]) * rstd[m] * gf + bf;
}

// ---------------------------------------------------------------------------
extern "C" void kernel_launch(void* const* d_in, const int* in_sizes, int n_in,
                              void* d_out, int out_size)
{
    const float* x     = (const float*)d_in[0];
    const float* mask  = (const float*)d_in[1];
    const float* posK  = (const float*)d_in[2];
    const float* posV  = (const float*)d_in[3];
    const float* timeK = (const float*)d_in[4];
    const float* timeV = (const float*)d_in[5];
    const float* Wq = (const float*)d_in[6];  const float* bq = (const float*)d_in[7];
    const float* Wk = (const float*)d_in[8];  const float* bk = (const float*)d_in[9];
    const float* Wv = (const float*)d_in[10]; const float* bv = (const float*)d_in[11];
    const float* ow = (const float*)d_in[12]; const float* ob = (const float*)d_in[13];
    const float* dw = (const float*)d_in[14]; const float* db = (const float*)d_in[15];
    const float* sca = (const float*)d_in[16];
    const float* Wd = (const float*)d_in[17]; const float* bd = (const float*)d_in[18];
    const float* lg = (const float*)d_in[19]; const float* lb = (const float*)d_in[20];

    dim3 g1(NBS / 8, 3);
    gemm3_kernel<<<g1, 256>>>(x, Wq, bq, Wk, bk, Wv, bv, posV);
    post_kernel<<<NBS / 8, 256>>>(posK, ow, dw);
    attn_kernel<<<NBS, 256>>>(timeK, timeV, mask, ob, db, sca);
    outln_kernel<<<NBS / 4, 256>>>(x, Wd, bd, lg, lb, (float*)d_out);
}

// round 12
// speedup vs baseline: 1.4620x; 1.0123x over previous
#include <cuda_runtime.h>
#include <math.h>

#define BB 8
#define SS 200
#define HH 4
#define DD 64
#define HID 256
#define NBS (BB*SS)   // 1600

// scratch (device globals; no allocation allowed)
__device__ float g_q[NBS*HID];
__device__ float g_kpos[NBS*HID];
__device__ float g_vpos[NBS*HID];
__device__ float g_qo[BB*HH*SS];
__device__ float g_ko[BB*HH*SS];
__device__ float g_qd[BB*HH*SS];
__device__ float g_kd[BB*HH*SS];
__device__ float g_ctx[NBS*HID];

// ---------------------------------------------------------------------------
// Kernel 1: QKV projection, 8 rows x one matrix per block, split-K x4.
// Epilogue: q-blocks compute qo/qd; k-blocks write kpos and compute ko/kd
// (post_kernel folded in). v-blocks write vpos.
// ---------------------------------------------------------------------------
__global__ __launch_bounds__(256) void gemm3_kernel(
    const float* __restrict__ x,
    const float* __restrict__ Wq, const float* __restrict__ bq,
    const float* __restrict__ Wk, const float* __restrict__ bk,
    const float* __restrict__ Wv, const float* __restrict__ bv,
    const float* __restrict__ posK, const float* __restrict__ posV,
    const float* __restrict__ order_w, const float* __restrict__ dist_w)
{
    const int r0  = blockIdx.x * 8;
    const int mat = blockIdx.y;
    const float* __restrict__ W    = (mat == 0) ? Wq : (mat == 1) ? Wk : Wv;
    const float* __restrict__ bias = (mat == 0) ? bq : (mat == 1) ? bk : bv;

    const int tid = threadIdx.x;
    const int s   = tid >> 6;
    const int c   = tid & 63;

    __shared__ float xs[HID][8];        // 8KB
    __shared__ float red[3][8][HID];    // 24KB
    __shared__ float fin[8][HID];       // 8KB raw q or k for dot epilogue

    for (int t = tid; t < 8 * HID; t += 256) {
        const int m = t >> 8, g = t & 255;
        xs[g][m] = x[(r0 + m) * HID + g];
    }
    __syncthreads();

    float4 acc[8];
    if (s == 0) {
        const float4 b4 = *(const float4*)&bias[4 * c];
        #pragma unroll
        for (int m = 0; m < 8; m++) acc[m] = b4;
    } else {
        #pragma unroll
        for (int m = 0; m < 8; m++) acc[m] = make_float4(0.f, 0.f, 0.f, 0.f);
    }

    const float* __restrict__ Wp = W + (size_t)(s * 64) * HID + 4 * c;
    const float* __restrict__ xp = &xs[s * 64][0];
    #pragma unroll 4
    for (int gi = 0; gi < 64; gi++) {
        const float4 w = *(const float4*)(Wp + (size_t)gi * HID);
        #pragma unroll
        for (int m = 0; m < 8; m++) {
            const float xv = xp[gi * 8 + m];
            acc[m].x += xv * w.x; acc[m].y += xv * w.y;
            acc[m].z += xv * w.z; acc[m].w += xv * w.w;
        }
    }

    if (s > 0) {
        #pragma unroll
        for (int m = 0; m < 8; m++)
            *(float4*)&red[s - 1][m][4 * c] = acc[m];
    }
    __syncthreads();

    if (s == 0) {
        #pragma unroll
        for (int m = 0; m < 8; m++) {
            const float4 r0v = *(const float4*)&red[0][m][4 * c];
            const float4 r1v = *(const float4*)&red[1][m][4 * c];
            const float4 r2v = *(const float4*)&red[2][m][4 * c];
            float4 a = acc[m];
            a.x += r0v.x + r1v.x + r2v.x;
            a.y += r0v.y + r1v.y + r2v.y;
            a.z += r0v.z + r1v.z + r2v.z;
            a.w += r0v.w + r1v.w + r2v.w;
            const int row = r0 + m;
            const size_t gidx = (size_t)row * HID + 4 * c;
            if (mat == 0) {
                *(float4*)&g_q[gidx] = a;
                *(float4*)&fin[m][4 * c] = a;
            } else if (mat == 1) {
                *(float4*)&fin[m][4 * c] = a;     // raw k for dots
                const float4 pk = *(const float4*)&posK[gidx];
                a.x += pk.x; a.y += pk.y; a.z += pk.z; a.w += pk.w;
                *(float4*)&g_kpos[gidx] = a;
            } else {
                const float4 pv = *(const float4*)&posV[gidx];
                a.x += pv.x; a.y += pv.y; a.z += pv.z; a.w += pv.w;
                *(float4*)&g_vpos[gidx] = a;
            }
        }
    }
    __syncthreads();

    // epilogue: order/dist dots. q-block -> qo/qd; k-block -> ko/kd.
    if (mat < 2) {
        const int w = tid >> 5, l = tid & 31;   // warp w handles row w
        const int obase = (mat == 1) ? 64 : 0;
        const float ow1 = order_w[obase + l], ow2 = order_w[obase + 32 + l];
        const float dw1 = dist_w[obase + l],  dw2 = dist_w[obase + 32 + l];
        const int row = r0 + w;
        const int b = row / SS, sidx = row % SS;
        #pragma unroll
        for (int h = 0; h < HH; h++) {
            const float v1 = fin[w][h * 64 + l];
            const float v2 = fin[w][h * 64 + 32 + l];
            float ao = v1 * ow1 + v2 * ow2;
            float ad = v1 * dw1 + v2 * dw2;
            #pragma unroll
            for (int off = 16; off; off >>= 1) {
                ao += __shfl_xor_sync(0xffffffffu, ao, off);
                ad += __shfl_xor_sync(0xffffffffu, ad, off);
            }
            if (l == 0) {
                const int idx = (b * HH + h) * SS + sidx;
                if (mat == 0) { g_qo[idx] = ao; g_qd[idx] = ad; }
                else          { g_ko[idx] = ao; g_kd[idx] = ad; }
            }
        }
    }
}

// ---------------------------------------------------------------------------
// Kernel 2: FUSED scores + softmax + ctx. ONE i-row per block (grid 1600),
// 256 threads. Probs never leave shared memory.
// ---------------------------------------------------------------------------
__global__ __launch_bounds__(256) void attn_kernel(
    const float* __restrict__ timeK, const float* __restrict__ timeV,
    const float* __restrict__ mask,
    const float* __restrict__ p_order_b, const float* __restrict__ p_dist_b,
    const float* __restrict__ p_scalar)
{
    const int tid = threadIdx.x;
    const int blk = blockIdx.x;
    const int b = blk / SS, i = blk % SS;
    const int w = tid >> 5, l = tid & 31;

    __shared__ float sc[HH][SS];       // scores -> exp (un-normalized)
    __shared__ float q_sh[HID];
    __shared__ float qos[HH], qds[HH];
    __shared__ float inv_s[HH];
    __shared__ float dl[SS];           // log(|d|+1) table
    __shared__ float4 part[3][64];     // ctx partials

    q_sh[tid] = g_q[((size_t)(b * SS + i)) * HID + tid];
    if (tid < HH) {
        qos[tid] = g_qo[(b * HH + tid) * SS + i];
        qds[tid] = g_qd[(b * HH + tid) * SS + i];
    }
    if (tid < SS) dl[tid] = __logf((float)tid + 1.f);
    __syncthreads();

    const float4 q0 = *(const float4*)&q_sh[l * 8];
    const float4 q1 = *(const float4*)&q_sh[l * 8 + 4];
    const int hh = l >> 3;

    const float* tkb = timeK + ((size_t)(b * SS + i)) * SS * HID;
    const float* kpb = g_kpos + (size_t)b * SS * HID;

    // ---- phase 1: raw scores  q . (timeK_ij + kpos_j) ----
    for (int j = w; j < SS; j += 8) {
        const float4* kp = (const float4*)(kpb + (size_t)j * HID);
        const float4* tk = (const float4*)(tkb + (size_t)j * HID);
        const float4 k0 = kp[2 * l], k1 = kp[2 * l + 1];
        const float4 t0 = tk[2 * l], t1 = tk[2 * l + 1];
        float p = q0.x * (t0.x + k0.x) + q0.y * (t0.y + k0.y)
                + q0.z * (t0.z + k0.z) + q0.w * (t0.w + k0.w)
                + q1.x * (t1.x + k1.x) + q1.y * (t1.y + k1.y)
                + q1.z * (t1.z + k1.z) + q1.w * (t1.w + k1.w);
        p += __shfl_xor_sync(0xffffffffu, p, 1);
        p += __shfl_xor_sync(0xffffffffu, p, 2);
        p += __shfl_xor_sync(0xffffffffu, p, 4);
        if ((l & 7) == 0) sc[hh][j] = p;
    }
    __syncthreads();

    // ---- phase 2: order/dist error terms, scale, mask ----
    const float order_b = *p_order_b;
    const float dist_b  = *p_dist_b;
    const float sc2 = p_scalar[0] * p_scalar[0] * 0.5f;
    for (int idx = tid; idx < HH * SS; idx += 256) {
        const int h = idx / SS, j = idx - (idx / SS) * SS;
        const float z = qos[h] + g_ko[(b * HH + h) * SS + j] + order_b;
        const float zz = (j > i) ? -z : z;     // log-sigmoid via softplus
        const float eo = -(fmaxf(zz, 0.f) + __logf(1.f + __expf(-fabsf(zz))));
        const float gd = dl[abs(j - i)];
        const float pd = qds[h] + g_kd[(b * HH + h) * SS + j] + dist_b;
        const float ed = -(gd - pd) * (gd - pd) * sc2;
        sc[h][j] = (sc[h][j] + eo + ed) * 0.125f
                 + mask[((size_t)b * SS + i) * SS + j];
    }
    __syncthreads();

    // ---- phase 3: softmax exp + sums ----
    if (w < HH) {
        float m = -1e30f;
        for (int j = l; j < SS; j += 32) m = fmaxf(m, sc[w][j]);
        #pragma unroll
        for (int off = 16; off; off >>= 1)
            m = fmaxf(m, __shfl_xor_sync(0xffffffffu, m, off));
        float sum = 0.f;
        for (int j = l; j < SS; j += 32) {
            const float e = __expf(sc[w][j] - m);
            sc[w][j] = e;
            sum += e;
        }
        #pragma unroll
        for (int off = 16; off; off >>= 1)
            sum += __shfl_xor_sync(0xffffffffu, sum, off);
        if (l == 0) inv_s[w] = 1.f / sum;
    }
    __syncthreads();

    // ---- phase 4: ctx accumulation (split-j x4); inv_s folded at end ----
    {
        const int grp = tid >> 6;
        const int fq  = tid & 63;
        const int h   = fq >> 4;

        const float4* tv = (const float4*)(timeV + ((size_t)(b * SS + i)) * SS * HID) + fq;
        const float4* vp = (const float4*)(g_vpos + (size_t)b * SS * HID) + fq;
        const float* prow = &sc[h][0];

        const int j0 = grp * (SS / 4);
        float4 acc = make_float4(0.f, 0.f, 0.f, 0.f);
        #pragma unroll 5
        for (int j = j0; j < j0 + SS / 4; j++) {
            const float p = prow[j];
            const float4 t4 = tv[(size_t)j * (HID / 4)];
            const float4 v4 = vp[(size_t)j * (HID / 4)];
            acc.x += p * (t4.x + v4.x);
            acc.y += p * (t4.y + v4.y);
            acc.z += p * (t4.z + v4.z);
            acc.w += p * (t4.w + v4.w);
        }

        if (grp > 0) part[grp - 1][fq] = acc;
        __syncthreads();
        if (grp == 0) {
            #pragma unroll
            for (int g = 0; g < 3; g++) {
                const float4 p4 = part[g][fq];
                acc.x += p4.x; acc.y += p4.y; acc.z += p4.z; acc.w += p4.w;
            }
            const float is = inv_s[h];
            acc.x *= is; acc.y *= is; acc.z *= is; acc.w *= is;
            *(float4*)&g_ctx[((size_t)(b * SS + i)) * HID + 4 * fq] = acc;
        }
    }
}

// ---------------------------------------------------------------------------
// Kernel 3: output projection, 4 rows/block, 512 threads split-K x8,
// grid 400, + residual + LN (fused).
// ---------------------------------------------------------------------------
__global__ __launch_bounds__(512) void outln_kernel(
    const float* __restrict__ x,
    const float* __restrict__ Wd, const float* __restrict__ bd,
    const float* __restrict__ ln_g, const float* __restrict__ ln_b,
    float* __restrict__ out)
{
    const int r0  = blockIdx.x * 4;
    const int tid = threadIdx.x;
    const int s   = tid >> 6;          // k-slice 0..7 (32 k each)
    const int c   = tid & 63;          // col quad

    __shared__ float cs[HID][4];        // 4KB
    __shared__ float red[7][4][HID];    // 28KB
    __shared__ float hsm[4][HID];       // 4KB
    __shared__ float mu[4], rstd[4];

    for (int t = tid; t < 4 * HID; t += 512) {
        const int m = t >> 8, g = t & 255;
        cs[g][m] = g_ctx[(size_t)(r0 + m) * HID + g];
    }
    __syncthreads();

    float4 acc[4];
    if (s == 0) {
        const float4 b4 = *(const float4*)&bd[4 * c];
        #pragma unroll
        for (int m = 0; m < 4; m++) acc[m] = b4;
    } else {
        #pragma unroll
        for (int m = 0; m < 4; m++) acc[m] = make_float4(0.f, 0.f, 0.f, 0.f);
    }

    const float* __restrict__ Wp = Wd + (size_t)(s * 32) * HID + 4 * c;
    const float* __restrict__ xp = &cs[s * 32][0];
    #pragma unroll 4
    for (int gi = 0; gi < 32; gi++) {
        const float4 w = *(const float4*)(Wp + (size_t)gi * HID);
        #pragma unroll
        for (int m = 0; m < 4; m++) {
            const float xv = xp[gi * 4 + m];
            acc[m].x += xv * w.x; acc[m].y += xv * w.y;
            acc[m].z += xv * w.z; acc[m].w += xv * w.w;
        }
    }

    if (s > 0) {
        #pragma unroll
        for (int m = 0; m < 4; m++)
            *(float4*)&red[s - 1][m][4 * c] = acc[m];
    }
    __syncthreads();

    if (s == 0) {
        #pragma unroll
        for (int m = 0; m < 4; m++) {
            float4 a = acc[m];
            #pragma unroll
            for (int p = 0; p < 7; p++) {
                const float4 r = *(const float4*)&red[p][m][4 * c];
                a.x += r.x; a.y += r.y; a.z += r.z; a.w += r.w;
            }
            const float4 xv = *(const float4*)&x[(size_t)(r0 + m) * HID + 4 * c];
            a.x += xv.x; a.y += xv.y; a.z += xv.z; a.w += xv.w;
            *(float4*)&hsm[m][4 * c] = a;
        }
    }
    __syncthreads();

    const int w = tid >> 5, l = tid & 31;
    if (w < 4) {
        float sum = 0.f, sum2 = 0.f;
        #pragma unroll
        for (int t = 0; t < 8; t++) {
            const float v = hsm[w][l + 32 * t];
            sum += v; sum2 += v * v;
        }
        #pragma unroll
        for (int off = 16; off; off >>= 1) {
            sum  += __shfl_xor_sync(0xffffffffu, sum,  off);
            sum2 += __shfl_xor_sync(0xffffffffu, sum2, off);
        }
        if (l == 0) {
            const float m_  = sum / HID;
            const float var = sum2 / HID - m_ * m_;
            mu[w]   = m_;
            rstd[w] = rsqrtf(var + 1e-12f);
        }
    }
    __syncthreads();

    if (tid < 256) {
        const int f = tid;
        const float gf = ln_g[f], bf = ln_b[f];
        #pragma unroll
        for (int m = 0; m < 4; m++)
            out[(size_t)(r0 + m) * HID + f] = (hsm[m][f] - mu[m]) * rstd[m] * gf + bf;
    }
}

// ---------------------------------------------------------------------------
extern "C" void kernel_launch(void* const* d_in, const int* in_sizes, int n_in,
                              void* d_out, int out_size)
{
    const float* x     = (const float*)d_in[0];
    const float* mask  = (const float*)d_in[1];
    const float* posK  = (const float*)d_in[2];
    const float* posV  = (const float*)d_in[3];
    const float* timeK = (const float*)d_in[4];
    const float* timeV = (const float*)d_in[5];
    const float* Wq = (const float*)d_in[6];  const float* bq = (const float*)d_in[7];
    const float* Wk = (const float*)d_in[8];  const float* bk = (const float*)d_in[9];
    const float* Wv = (const float*)d_in[10]; const float* bv = (const float*)d_in[11];
    const float* ow = (const float*)d_in[12]; const float* ob = (const float*)d_in[13];
    const float* dw = (const float*)d_in[14]; const float* db = (const float*)d_in[15];
    const float* sca = (const float*)d_in[16];
    const float* Wd = (const float*)d_in[17]; const float* bd = (const float*)d_in[18];
    const float* lg = (const float*)d_in[19]; const float* lb = (const float*)d_in[20];

    dim3 g1(NBS / 8, 3);
    gemm3_kernel<<<g1, 256>>>(x, Wq, bq, Wk, bk, Wv, bv, posK, posV, ow, dw);
    attn_kernel<<<NBS, 256>>>(timeK, timeV, mask, ob, db, sca);
    outln_kernel<<<NBS / 4, 512>>>(x, Wd, bd, lg, lb, (float*)d_out);
}